// round 2
// baseline (speedup 1.0000x reference)
#include <cuda_runtime.h>
#include <cuda_bf16.h>
#include <math.h>

// Problem constants
#define VOCAB 32000
#define D_IN  512
#define D_H   1024
#define D_OUT 64
#define BB    64
#define SS    256
#define M_TOT (BB * SS)          // 16384 rows, m = s*64 + b
#define G3H   (3 * D_H)          // 3072

// Scratch (device globals — no allocation allowed)
__device__ float g_gi[(size_t)M_TOT * G3H];   // [S][B][3H]  192 MB
__device__ float g_hs[(size_t)M_TOT * D_H];   // [S][B][H]    64 MB

// ---------------------------------------------------------------------------
// Kernel A: fused embedding gather + input projection GEMM
//   gi[m][n] = sum_k emb[tok(m)][k] * w_ih[n][k] + b_ih[n]
//   m = s*64 + b, tok(m) = x[b*256 + s]
// Tile 128x128, BK=16, 256 threads, 8x8 microtile, float4 smem reads.
// ---------------------------------------------------------------------------
__global__ void k_embed_gi(const int* __restrict__ x,
                           const float* __restrict__ emb,
                           const float* __restrict__ w_ih,
                           const float* __restrict__ b_ih) {
    __shared__ float As[16][136];   // [kk][mm], pad 136: 4-way write conflicts, aligned float4 reads
    __shared__ float Ws[16][136];   // [kk][nn]
    __shared__ int   tok[128];

    const int m0 = blockIdx.y * 128;
    const int n0 = blockIdx.x * 128;
    const int tid = threadIdx.x;
    const int tx = tid & 15;
    const int ty = tid >> 4;

    if (tid < 128) {
        int m = m0 + tid;
        tok[tid] = x[(m & 63) * SS + (m >> 6)];
    }
    __syncthreads();

    float acc[8][8];
#pragma unroll
    for (int i = 0; i < 8; i++)
#pragma unroll
        for (int j = 0; j < 8; j++) acc[i][j] = 0.f;

    for (int k0 = 0; k0 < D_IN; k0 += 16) {
        // Load A tile (gathered): consecutive tid -> consecutive kk (coalesced 64B per row)
#pragma unroll
        for (int i = tid; i < 2048; i += 256) {
            int mm = i >> 4, kk = i & 15;
            As[kk][mm] = emb[(size_t)tok[mm] * D_IN + k0 + kk];
        }
#pragma unroll
        for (int i = tid; i < 2048; i += 256) {
            int nn = i >> 4, kk = i & 15;
            Ws[kk][nn] = w_ih[(size_t)(n0 + nn) * D_IN + k0 + kk];
        }
        __syncthreads();

#pragma unroll
        for (int kk = 0; kk < 16; kk++) {
            float a[8], w[8];
            *(float4*)&a[0] = *(const float4*)&As[kk][ty * 8];
            *(float4*)&a[4] = *(const float4*)&As[kk][ty * 8 + 4];
            *(float4*)&w[0] = *(const float4*)&Ws[kk][tx * 8];
            *(float4*)&w[4] = *(const float4*)&Ws[kk][tx * 8 + 4];
#pragma unroll
            for (int i = 0; i < 8; i++)
#pragma unroll
                for (int j = 0; j < 8; j++) acc[i][j] += a[i] * w[j];
        }
        __syncthreads();
    }

    float bias[8];
#pragma unroll
    for (int j = 0; j < 8; j++) bias[j] = b_ih[n0 + tx * 8 + j];

#pragma unroll
    for (int i = 0; i < 8; i++) {
        size_t row = (size_t)(m0 + ty * 8 + i) * G3H + n0 + tx * 8;
        float4 v0 = make_float4(acc[i][0] + bias[0], acc[i][1] + bias[1],
                                acc[i][2] + bias[2], acc[i][3] + bias[3]);
        float4 v1 = make_float4(acc[i][4] + bias[4], acc[i][5] + bias[5],
                                acc[i][6] + bias[6], acc[i][7] + bias[7]);
        *(float4*)&g_gi[row]     = v0;
        *(float4*)&g_gi[row + 4] = v1;
    }
}

// ---------------------------------------------------------------------------
// Kernel B: one GRU timestep (fused gh GEMM + gate nonlinearity + h update)
//   grid = 128 CTAs (8 j-values each, x3 gates = 24 rows of w_hh), 128 threads
//   CTA computes gh[64][24], K=1024 in BK=32 chunks; epilogue applies gates.
//   Row index within CTA: r = jj*3 + g so each thread owns all 3 gates of its j's.
// ---------------------------------------------------------------------------
__global__ void k_gru_step(int s,
                           const float* __restrict__ w_hh,
                           const float* __restrict__ b_hh) {
    __shared__ float h_s[32][65];   // [kk][b]
    __shared__ float w_s[24][33];   // [r][kk]

    const int j0  = blockIdx.x * 8;
    const int tid = threadIdx.x;        // 128
    const int tb  = tid & 31;           // batch group: b in {tb, tb+32}
    const int tr  = tid >> 5;           // 0..3: rows 6*tr .. 6*tr+5 (jj in {2tr,2tr+1})

    const float* hp = (s == 0) ? nullptr : (g_hs + (size_t)(s - 1) * BB * D_H);

    float acc[2][6];
#pragma unroll
    for (int a = 0; a < 2; a++)
#pragma unroll
        for (int q = 0; q < 6; q++) acc[a][q] = 0.f;

    for (int k0 = 0; k0 < D_H; k0 += 32) {
        if (hp) {
#pragma unroll
            for (int i = tid; i < 2048; i += 128) {
                int b = i >> 5, kk = i & 31;
                h_s[kk][b] = hp[(size_t)b * D_H + k0 + kk];
            }
        } else {
#pragma unroll
            for (int i = tid; i < 2048; i += 128) {
                int b = i >> 5, kk = i & 31;
                h_s[kk][b] = 0.f;
            }
        }
#pragma unroll
        for (int i = tid; i < 768; i += 128) {
            int r = i >> 5, kk = i & 31;
            int g = r % 3, jj = r / 3;
            w_s[r][kk] = w_hh[(size_t)(g * D_H + j0 + jj) * D_H + k0 + kk];
        }
        __syncthreads();

#pragma unroll
        for (int kk = 0; kk < 32; kk++) {
            float h0 = h_s[kk][tb];
            float h1 = h_s[kk][tb + 32];
#pragma unroll
            for (int q = 0; q < 6; q++) {
                float wv = w_s[tr * 6 + q][kk];
                acc[0][q] += h0 * wv;
                acc[1][q] += h1 * wv;
            }
        }
        __syncthreads();
    }

    // Epilogue: gates + hidden update
#pragma unroll
    for (int bi = 0; bi < 2; bi++) {
        int b = tb + bi * 32;
        const float* gi = g_gi + (size_t)(s * BB + b) * G3H;
#pragma unroll
        for (int u = 0; u < 2; u++) {
            int j = j0 + tr * 2 + u;
            float ghr = acc[bi][u * 3 + 0] + b_hh[j];
            float ghz = acc[bi][u * 3 + 1] + b_hh[D_H + j];
            float ghn = acc[bi][u * 3 + 2] + b_hh[2 * D_H + j];
            float r = 1.f / (1.f + expf(-(gi[j] + ghr)));
            float z = 1.f / (1.f + expf(-(gi[D_H + j] + ghz)));
            float n = tanhf(gi[2 * D_H + j] + r * ghn);
            float hprev = (s == 0) ? 0.f : hp[(size_t)b * D_H + j];
            g_hs[(size_t)(s * BB + b) * D_H + j] = (1.f - z) * n + z * hprev;
        }
    }
}

// ---------------------------------------------------------------------------
// Kernel C: FC (N=64 full per CTA) + fused log_softmax over the 64 outputs.
//   CTA: 32 rows x 64 outputs, K=1024 (BK=32). 256 threads, 2x4 microtile.
// ---------------------------------------------------------------------------
__global__ void k_fc_lsm(const float* __restrict__ fc_w,
                         const float* __restrict__ fc_b,
                         float* __restrict__ out) {
    __shared__ float h_s[32][33];   // [kk][mm]
    __shared__ float w_s[32][65];   // [kk][o]
    __shared__ float ls[32][65];    // logits
    __shared__ float rowred[32];

    const int m0  = blockIdx.x * 32;
    const int tid = threadIdx.x;    // 256
    const int to  = tid & 15;       // o in {to, to+16, to+32, to+48}
    const int tm  = tid >> 4;       // m in {tm, tm+16}

    float acc[2][4];
#pragma unroll
    for (int a = 0; a < 2; a++)
#pragma unroll
        for (int q = 0; q < 4; q++) acc[a][q] = 0.f;

    for (int k0 = 0; k0 < D_H; k0 += 32) {
#pragma unroll
        for (int i = tid; i < 1024; i += 256) {
            int mm = i >> 5, kk = i & 31;
            h_s[kk][mm] = g_hs[(size_t)(m0 + mm) * D_H + k0 + kk];
        }
#pragma unroll
        for (int i = tid; i < 2048; i += 256) {
            int o = i >> 5, kk = i & 31;
            w_s[kk][o] = fc_w[(size_t)o * D_H + k0 + kk];
        }
        __syncthreads();

#pragma unroll
        for (int kk = 0; kk < 32; kk++) {
            float a0 = h_s[kk][tm];
            float a1 = h_s[kk][tm + 16];
#pragma unroll
            for (int q = 0; q < 4; q++) {
                float w = w_s[kk][to + 16 * q];
                acc[0][q] += a0 * w;
                acc[1][q] += a1 * w;
            }
        }
        __syncthreads();
    }

#pragma unroll
    for (int mi = 0; mi < 2; mi++)
#pragma unroll
        for (int q = 0; q < 4; q++)
            ls[tm + 16 * mi][to + 16 * q] = acc[mi][q] + fc_b[to + 16 * q];
    __syncthreads();

    if (tid < 32) {
        float mx = -1e30f;
#pragma unroll 8
        for (int o = 0; o < 64; o++) mx = fmaxf(mx, ls[tid][o]);
        float ssum = 0.f;
#pragma unroll 8
        for (int o = 0; o < 64; o++) ssum += expf(ls[tid][o] - mx);
        rowred[tid] = mx + logf(ssum);
    }
    __syncthreads();

    for (int i = tid; i < 32 * 64; i += 256) {
        int mm = i >> 6, o = i & 63;
        int m = m0 + mm;
        int b = m & 63, sIdx = m >> 6;
        out[((size_t)b * SS + sIdx) * D_OUT + o] = ls[mm][o] - rowred[mm];
    }
}

// ---------------------------------------------------------------------------
// Launch: inputs in setup_inputs order:
//   0:x(int32) 1:emb 2:w_ih 3:w_hh 4:b_ih 5:b_hh 6:fc_w 7:fc_b
// ---------------------------------------------------------------------------
extern "C" void kernel_launch(void* const* d_in, const int* in_sizes, int n_in,
                              void* d_out, int out_size) {
    const int*   x    = (const int*)  d_in[0];
    const float* emb  = (const float*)d_in[1];
    const float* w_ih = (const float*)d_in[2];
    const float* w_hh = (const float*)d_in[3];
    const float* b_ih = (const float*)d_in[4];
    const float* b_hh = (const float*)d_in[5];
    const float* fc_w = (const float*)d_in[6];
    const float* fc_b = (const float*)d_in[7];
    float* out = (float*)d_out;

    // A: embedding + input projection, [16384 x 3072] = 51.5 GFLOP
    k_embed_gi<<<dim3(G3H / 128, M_TOT / 128), 256>>>(x, emb, w_ih, b_ih);

    // B: 256 sequential GRU steps
    for (int s = 0; s < SS; s++) {
        k_gru_step<<<D_H / 8, 128>>>(s, w_hh, b_hh);
    }

    // C: FC + log_softmax
    k_fc_lsm<<<M_TOT / 32, 256>>>(fc_w, fc_b, out);
}

// round 3
// speedup vs baseline: 3.3051x; 3.3051x over previous
#include <cuda_runtime.h>
#include <cuda_bf16.h>
#include <math.h>

// Problem constants
#define VOCAB 32000
#define D_IN  512
#define D_H   1024
#define D_OUT 64
#define BB    64
#define SS    256
#define M_TOT (BB * SS)          // 16384 rows, m = s*64 + b
#define G3H   (3 * D_H)          // 3072
#define GRID  128                // persistent CTAs (1 per SM, co-resident)

// Scratch (device globals — no allocation allowed)
__device__ float g_gi[(size_t)M_TOT * G3H];   // [S][B][3H]  192 MB
__device__ float g_hs[(size_t)M_TOT * D_H];   // [S][B][H]    64 MB
__device__ float g_hzero[BB * D_H];           // stays zero (never written)

// Grid-barrier state (reset each launch by k_reset)
__device__ unsigned g_cnt;
__device__ volatile unsigned g_gen;

__global__ void k_reset() { g_cnt = 0; g_gen = 0; }

// ---------------------------------------------------------------------------
// Kernel A: fused embedding gather + input projection GEMM
//   gi[m][n] = sum_k emb[tok(m)][k] * w_ih[n][k] + b_ih[n]
//   m = s*64 + b, tok(m) = x[b*256 + s]
// ---------------------------------------------------------------------------
__global__ void k_embed_gi(const int* __restrict__ x,
                           const float* __restrict__ emb,
                           const float* __restrict__ w_ih,
                           const float* __restrict__ b_ih) {
    __shared__ float As[16][136];
    __shared__ float Ws[16][136];
    __shared__ int   tok[128];

    const int m0 = blockIdx.y * 128;
    const int n0 = blockIdx.x * 128;
    const int tid = threadIdx.x;
    const int tx = tid & 15;
    const int ty = tid >> 4;

    if (tid < 128) {
        int m = m0 + tid;
        tok[tid] = x[(m & 63) * SS + (m >> 6)];
    }
    __syncthreads();

    float acc[8][8];
#pragma unroll
    for (int i = 0; i < 8; i++)
#pragma unroll
        for (int j = 0; j < 8; j++) acc[i][j] = 0.f;

    for (int k0 = 0; k0 < D_IN; k0 += 16) {
#pragma unroll
        for (int i = tid; i < 2048; i += 256) {
            int mm = i >> 4, kk = i & 15;
            As[kk][mm] = emb[(size_t)tok[mm] * D_IN + k0 + kk];
        }
#pragma unroll
        for (int i = tid; i < 2048; i += 256) {
            int nn = i >> 4, kk = i & 15;
            Ws[kk][nn] = w_ih[(size_t)(n0 + nn) * D_IN + k0 + kk];
        }
        __syncthreads();

#pragma unroll
        for (int kk = 0; kk < 16; kk++) {
            float a[8], w[8];
            *(float4*)&a[0] = *(const float4*)&As[kk][ty * 8];
            *(float4*)&a[4] = *(const float4*)&As[kk][ty * 8 + 4];
            *(float4*)&w[0] = *(const float4*)&Ws[kk][tx * 8];
            *(float4*)&w[4] = *(const float4*)&Ws[kk][tx * 8 + 4];
#pragma unroll
            for (int i = 0; i < 8; i++)
#pragma unroll
                for (int j = 0; j < 8; j++) acc[i][j] += a[i] * w[j];
        }
        __syncthreads();
    }

    float bias[8];
#pragma unroll
    for (int j = 0; j < 8; j++) bias[j] = b_ih[n0 + tx * 8 + j];

#pragma unroll
    for (int i = 0; i < 8; i++) {
        size_t row = (size_t)(m0 + ty * 8 + i) * G3H + n0 + tx * 8;
        float4 v0 = make_float4(acc[i][0] + bias[0], acc[i][1] + bias[1],
                                acc[i][2] + bias[2], acc[i][3] + bias[3]);
        float4 v1 = make_float4(acc[i][4] + bias[4], acc[i][5] + bias[5],
                                acc[i][6] + bias[6], acc[i][7] + bias[7]);
        *(float4*)&g_gi[row]     = v0;
        *(float4*)&g_gi[row + 4] = v1;
    }
}

// ---------------------------------------------------------------------------
// Kernel B: PERSISTENT GRU — all 256 steps in one kernel.
//   128 CTAs x 256 threads. CTA bid owns j in [bid*8, bid*8+8): 24 w_hh rows
//   (96 KB) cached in SMEM for the whole sequence. Per step: stream h_prev
//   through double-buffered 32 KB chunks, FMA in SMEM, gate epilogue, write
//   h slice, custom grid barrier.
//   Thread map: lane=tid&31, wgrp=tid>>5 (8 warps).
//     b    = lane + 32*(wgrp&1)            (1 batch element per thread)
//     rgrp = wgrp>>1  -> rows r0=rgrp*6..+5 == j-pair jj0=rgrp*2 (3 gates ea.)
//   w_s reads are warp-uniform (broadcast); h_s reads conflict-free.
// ---------------------------------------------------------------------------
__global__ void k_gru_persist(const float* __restrict__ w_hh,
                              const float* __restrict__ b_hh) {
    extern __shared__ float sm[];
    float* w_s = sm;                   // [24][1024]  = 96 KB
    float* h_s = sm + 24 * 1024;       // [2][128][64] = 64 KB

    const int tid  = threadIdx.x;      // 256
    const int bid  = blockIdx.x;       // 128
    const int j0   = bid * 8;
    const int lane = tid & 31;
    const int wgrp = tid >> 5;
    const int b    = lane + 32 * (wgrp & 1);
    const int rgrp = wgrp >> 1;
    const int r0   = rgrp * 6;
    const int jj0  = rgrp * 2;
    const int b_l  = tid & 63;         // loader batch index
    const int half = tid >> 6;         // loader k-quarter

    // One-time: load w_hh slice into SMEM. Row r = jj*3 + g.
    for (int i = tid; i < 24 * 256; i += 256) {
        int r = i >> 8, kq = i & 255;
        int g = r % 3, jj = r / 3;
        float4 v = *(const float4*)&w_hh[(size_t)(g * D_H + j0 + jj) * D_H + kq * 4];
        *(float4*)&w_s[r * 1024 + kq * 4] = v;
    }
    float bh[6];
#pragma unroll
    for (int u = 0; u < 2; u++)
#pragma unroll
        for (int g = 0; g < 3; g++)
            bh[u * 3 + g] = b_hh[g * D_H + j0 + jj0 + u];
    __syncthreads();

    for (int s = 0; s < SS; s++) {
        const float* hp = (s == 0) ? g_hzero : (g_hs + (size_t)(s - 1) * BB * D_H);
        float* ho = g_hs + (size_t)s * BB * D_H;
        const float* gi = g_gi + ((size_t)s * BB + b) * G3H;

        // Prefetch epilogue operands (hidden under the GEMM)
        float giv[6], hpv[2];
#pragma unroll
        for (int u = 0; u < 2; u++) {
            hpv[u] = hp[(size_t)b * D_H + j0 + jj0 + u];
#pragma unroll
            for (int g = 0; g < 3; g++)
                giv[u * 3 + g] = gi[g * D_H + j0 + jj0 + u];
        }

        float acc[6] = {0.f, 0.f, 0.f, 0.f, 0.f, 0.f};

        // Load chunk 0
        {
            const float* src = &hp[(size_t)b_l * D_H + half * 32];
#pragma unroll
            for (int q = 0; q < 8; q++) {
                float4 v = *(const float4*)&src[q * 4];
                float* dst = &h_s[(half * 32 + q * 4) * 64 + b_l];
                dst[0] = v.x; dst[64] = v.y; dst[128] = v.z; dst[192] = v.w;
            }
        }
        __syncthreads();

        for (int c = 0; c < 8; c++) {
            const int buf = c & 1;
            if (c < 7) {  // prefetch next chunk into the other buffer
                const float* src = &hp[(size_t)b_l * D_H + (c + 1) * 128 + half * 32];
                float* dbase = &h_s[(buf ^ 1) * 8192 + (half * 32) * 64 + b_l];
#pragma unroll
                for (int q = 0; q < 8; q++) {
                    float4 v = *(const float4*)&src[q * 4];
                    float* dst = dbase + q * 256;
                    dst[0] = v.x; dst[64] = v.y; dst[128] = v.z; dst[192] = v.w;
                }
            }
            const int k0 = c * 128;
            const float* hc = &h_s[buf * 8192];
#pragma unroll 4
            for (int kk = 0; kk < 128; kk += 4) {
                float h0 = hc[(kk + 0) * 64 + b];
                float h1 = hc[(kk + 1) * 64 + b];
                float h2 = hc[(kk + 2) * 64 + b];
                float h3 = hc[(kk + 3) * 64 + b];
#pragma unroll
                for (int q = 0; q < 6; q++) {
                    float4 wv = *(const float4*)&w_s[(r0 + q) * 1024 + k0 + kk];
                    acc[q] += h0 * wv.x;
                    acc[q] += h1 * wv.y;
                    acc[q] += h2 * wv.z;
                    acc[q] += h3 * wv.w;
                }
            }
            __syncthreads();
        }

        // Gate epilogue + h update
#pragma unroll
        for (int u = 0; u < 2; u++) {
            float r = 1.f / (1.f + expf(-(giv[u * 3 + 0] + acc[u * 3 + 0] + bh[u * 3 + 0])));
            float z = 1.f / (1.f + expf(-(giv[u * 3 + 1] + acc[u * 3 + 1] + bh[u * 3 + 1])));
            float n = tanhf(giv[u * 3 + 2] + r * (acc[u * 3 + 2] + bh[u * 3 + 2]));
            ho[(size_t)b * D_H + j0 + jj0 + u] = (1.f - z) * n + z * hpv[u];
        }

        // Grid barrier (sense via monotonically increasing generation)
        __syncthreads();
        if (tid == 0) {
            __threadfence();
            unsigned a = atomicAdd(&g_cnt, 1u);
            if (a == (unsigned)((s + 1) * GRID - 1)) {
                g_gen = (unsigned)(s + 1);
            } else {
                while (g_gen < (unsigned)(s + 1)) { }
            }
        }
        __syncthreads();
    }
}

// ---------------------------------------------------------------------------
// Kernel C: FC (N=64 full per CTA) + fused log_softmax over the 64 outputs.
// ---------------------------------------------------------------------------
__global__ void k_fc_lsm(const float* __restrict__ fc_w,
                         const float* __restrict__ fc_b,
                         float* __restrict__ out) {
    __shared__ float h_s[32][33];
    __shared__ float w_s[32][65];
    __shared__ float ls[32][65];
    __shared__ float rowred[32];

    const int m0  = blockIdx.x * 32;
    const int tid = threadIdx.x;    // 256
    const int to  = tid & 15;
    const int tm  = tid >> 4;

    float acc[2][4];
#pragma unroll
    for (int a = 0; a < 2; a++)
#pragma unroll
        for (int q = 0; q < 4; q++) acc[a][q] = 0.f;

    for (int k0 = 0; k0 < D_H; k0 += 32) {
#pragma unroll
        for (int i = tid; i < 1024; i += 256) {
            int mm = i >> 5, kk = i & 31;
            h_s[kk][mm] = g_hs[(size_t)(m0 + mm) * D_H + k0 + kk];
        }
#pragma unroll
        for (int i = tid; i < 2048; i += 256) {
            int o = i >> 5, kk = i & 31;
            w_s[kk][o] = fc_w[(size_t)o * D_H + k0 + kk];
        }
        __syncthreads();

#pragma unroll
        for (int kk = 0; kk < 32; kk++) {
            float a0 = h_s[kk][tm];
            float a1 = h_s[kk][tm + 16];
#pragma unroll
            for (int q = 0; q < 4; q++) {
                float w = w_s[kk][to + 16 * q];
                acc[0][q] += a0 * w;
                acc[1][q] += a1 * w;
            }
        }
        __syncthreads();
    }

#pragma unroll
    for (int mi = 0; mi < 2; mi++)
#pragma unroll
        for (int q = 0; q < 4; q++)
            ls[tm + 16 * mi][to + 16 * q] = acc[mi][q] + fc_b[to + 16 * q];
    __syncthreads();

    if (tid < 32) {
        float mx = -1e30f;
#pragma unroll 8
        for (int o = 0; o < 64; o++) mx = fmaxf(mx, ls[tid][o]);
        float ssum = 0.f;
#pragma unroll 8
        for (int o = 0; o < 64; o++) ssum += expf(ls[tid][o] - mx);
        rowred[tid] = mx + logf(ssum);
    }
    __syncthreads();

    for (int i = tid; i < 32 * 64; i += 256) {
        int mm = i >> 6, o = i & 63;
        int m = m0 + mm;
        int b = m & 63, sIdx = m >> 6;
        out[((size_t)b * SS + sIdx) * D_OUT + o] = ls[mm][o] - rowred[mm];
    }
}

// ---------------------------------------------------------------------------
// Launch: inputs in setup_inputs order:
//   0:x(int32) 1:emb 2:w_ih 3:w_hh 4:b_ih 5:b_hh 6:fc_w 7:fc_b
// ---------------------------------------------------------------------------
extern "C" void kernel_launch(void* const* d_in, const int* in_sizes, int n_in,
                              void* d_out, int out_size) {
    const int*   x    = (const int*)  d_in[0];
    const float* emb  = (const float*)d_in[1];
    const float* w_ih = (const float*)d_in[2];
    const float* w_hh = (const float*)d_in[3];
    const float* b_ih = (const float*)d_in[4];
    const float* b_hh = (const float*)d_in[5];
    const float* fc_w = (const float*)d_in[6];
    const float* fc_b = (const float*)d_in[7];
    float* out = (float*)d_out;

    static bool attr_set = false;
    if (!attr_set) {
        cudaFuncSetAttribute(k_gru_persist,
                             cudaFuncAttributeMaxDynamicSharedMemorySize,
                             (24 * 1024 + 2 * 128 * 64) * sizeof(float));
        attr_set = true;
    }

    // Reset grid-barrier state (part of the captured graph -> every replay)
    k_reset<<<1, 1>>>();

    // A: embedding + input projection, [16384 x 3072] = 51.5 GFLOP
    k_embed_gi<<<dim3(G3H / 128, M_TOT / 128), 256>>>(x, emb, w_ih, b_ih);

    // B: persistent GRU over all 256 steps
    k_gru_persist<<<GRID, 256, (24 * 1024 + 2 * 128 * 64) * sizeof(float)>>>(w_hh, b_hh);

    // C: FC + log_softmax
    k_fc_lsm<<<M_TOT / 32, 256>>>(fc_w, fc_b, out);
}